// round 3
// baseline (speedup 1.0000x reference)
#include <cuda_runtime.h>
#include <math.h>

#define BATCH   1024
#define IN_DIM  256
#define NG      512
#define OUT_DIM 256
#define KCAT    512   // concatenated K for GEMM1: [x^2 ; x]

// ---- scratch (device globals; no allocation allowed) ----
__device__ float g_Bc[NG * KCAT];     // row g: [-0.5*inv_s2 (256) | c*inv_s2 (256)]
__device__ float g_cst[NG];           // -0.5 * sum c^2 * inv_s2
__device__ float g_xcat[BATCH * KCAT];
__device__ float g_gauss[BATCH * NG];

// one block per gaussian, 256 threads (= IN_DIM)
__global__ void prep_kernel(const float* __restrict__ centers,
                            const float* __restrict__ stds) {
    int g = blockIdx.x;
    int k = threadIdx.x;
    float c = centers[g * IN_DIM + k];
    float s = stds[g * IN_DIM + k];
    float inv = 1.0f / (s * s);
    g_Bc[g * KCAT + k]          = -0.5f * inv;
    g_Bc[g * KCAT + IN_DIM + k] = c * inv;

    __shared__ float red[256];
    red[k] = c * c * inv;
    __syncthreads();
    #pragma unroll
    for (int off = 128; off > 0; off >>= 1) {
        if (k < off) red[k] += red[k + off];
        __syncthreads();
    }
    if (k == 0) g_cst[g] = -0.5f * red[0];
}

__global__ void xcat_kernel(const float* __restrict__ x) {
    int i = blockIdx.x * blockDim.x + threadIdx.x;
    if (i < BATCH * IN_DIM) {
        int b = i / IN_DIM, k = i % IN_DIM;
        float v = x[i];
        g_xcat[b * KCAT + k]          = v * v;
        g_xcat[b * KCAT + IN_DIM + k] = v;
    }
}

#define BM 64
#define BN 64
#define BK 16

// BT=true : B is [N][K] row-major (NT gemm).  BT=false : B is [K][N] (NN gemm).
// DOEXP   : epilogue C = expf(acc + bias[n]); else C = acc.
template <bool BT, bool DOEXP>
__device__ __forceinline__ void gemm_body(const float* __restrict__ A,
                                          const float* __restrict__ B,
                                          const float* __restrict__ bias,
                                          float* __restrict__ C,
                                          int M, int N, int K) {
    __shared__ float As[BK][BM + 4];
    __shared__ float Bs[BK][BN + 4];
    int tid = threadIdx.x;
    int tx = tid & 15;        // 0..15  -> n microtile
    int ty = tid >> 4;        // 0..15  -> m microtile
    int m0 = blockIdx.y * BM;
    int n0 = blockIdx.x * BN;

    float acc[4][4] = {};

    int aRow  = tid >> 2;          // 0..63 (m)
    int aCol  = (tid & 3) << 2;    // 0,4,8,12 (k)
    int bRowN = tid >> 2;          // NT: 0..63 (n)
    int bColK = (tid & 3) << 2;    // NT: k
    int bRowK = tid >> 4;          // NN: 0..15 (k)
    int bColN = (tid & 15) << 2;   // NN: n

    for (int k0 = 0; k0 < K; k0 += BK) {
        float4 av = *reinterpret_cast<const float4*>(&A[(m0 + aRow) * K + k0 + aCol]);
        As[aCol + 0][aRow] = av.x;
        As[aCol + 1][aRow] = av.y;
        As[aCol + 2][aRow] = av.z;
        As[aCol + 3][aRow] = av.w;
        if (BT) {
            float4 bv = *reinterpret_cast<const float4*>(&B[(n0 + bRowN) * K + k0 + bColK]);
            Bs[bColK + 0][bRowN] = bv.x;
            Bs[bColK + 1][bRowN] = bv.y;
            Bs[bColK + 2][bRowN] = bv.z;
            Bs[bColK + 3][bRowN] = bv.w;
        } else {
            float4 bv = *reinterpret_cast<const float4*>(&B[(k0 + bRowK) * N + n0 + bColN]);
            *reinterpret_cast<float4*>(&Bs[bRowK][bColN]) = bv;
        }
        __syncthreads();

        #pragma unroll
        for (int k = 0; k < BK; k++) {
            float ra[4], rb[4];
            #pragma unroll
            for (int i = 0; i < 4; i++) ra[i] = As[k][ty * 4 + i];
            #pragma unroll
            for (int j = 0; j < 4; j++) rb[j] = Bs[k][tx * 4 + j];
            #pragma unroll
            for (int i = 0; i < 4; i++)
                #pragma unroll
                for (int j = 0; j < 4; j++)
                    acc[i][j] = fmaf(ra[i], rb[j], acc[i][j]);
        }
        __syncthreads();
    }

    #pragma unroll
    for (int i = 0; i < 4; i++) {
        int m = m0 + ty * 4 + i;
        #pragma unroll
        for (int j = 0; j < 4; j++) {
            int n = n0 + tx * 4 + j;
            float v = acc[i][j];
            if (DOEXP) v = expf(v + bias[n]);
            C[m * N + n] = v;
        }
    }
}

// GEMM1: gauss[b][g] = exp( xcat[b,:] . Bc[g,:] + cst[g] )   (NT, K=512)
__global__ void __launch_bounds__(256)
gemm1_kernel() {
    gemm_body<true, true>(g_xcat, g_Bc, g_cst, g_gauss, BATCH, NG, KCAT);
}

// GEMM2: out[b][o] = gauss[b,:] . W[:,o]   (NN, K=512)
__global__ void __launch_bounds__(256)
gemm2_kernel(const float* __restrict__ W, float* __restrict__ out) {
    gemm_body<false, false>(g_gauss, W, nullptr, out, BATCH, OUT_DIM, NG);
}

extern "C" void kernel_launch(void* const* d_in, const int* in_sizes, int n_in,
                              void* d_out, int out_size) {
    const float* x       = (const float*)d_in[0];
    const float* centers = (const float*)d_in[1];
    const float* stds    = (const float*)d_in[2];
    const float* weights = (const float*)d_in[3];
    float* out = (float*)d_out;

    prep_kernel<<<NG, 256>>>(centers, stds);
    xcat_kernel<<<(BATCH * IN_DIM + 255) / 256, 256>>>(x);
    gemm1_kernel<<<dim3(NG / BN, BATCH / BM), 256>>>();
    gemm2_kernel<<<dim3(OUT_DIM / BN, BATCH / BM), 256>>>(weights, out);
}

// round 5
// speedup vs baseline: 2.4380x; 2.4380x over previous
#include <cuda_runtime.h>
#include <math.h>
#include <stdint.h>

#define BATCH   1024
#define IN_DIM  256
#define NG      512
#define OUT_DIM 256
#define CAP     2048.0f
#define SLOTS   16

// ---- device scratch (no allocation allowed) ----
__device__ float g_B1[NG * IN_DIM];   // c * min(1/s^2, CAP)
__device__ float g_B2[NG * IN_DIM];   // -0.5 * min(1/s^2, CAP)
__device__ float g_cst[NG];           // -0.5 * sum c^2 * min(inv, CAP)
__device__ int   g_cnt[NG];           // excess-coord count per gaussian
__device__ float g_le[NG * SLOTS];    // -0.5*(inv - CAP)   (excess, <= 0)
__device__ float g_lc[NG * SLOTS];    // c at that coord
__device__ int   g_lk[NG * SLOTS];    // k index
__device__ __align__(16) float g_gauss[BATCH * NG];

__device__ __forceinline__ uint32_t fbits(float f) { return __float_as_uint(f); }

__device__ __forceinline__ void mma_tf32(float d[4],
    uint32_t a0, uint32_t a1, uint32_t a2, uint32_t a3,
    uint32_t b0, uint32_t b1) {
    asm volatile(
        "mma.sync.aligned.m16n8k8.row.col.f32.tf32.tf32.f32 "
        "{%0,%1,%2,%3}, {%4,%5,%6,%7}, {%8,%9}, {%0,%1,%2,%3};\n"
        : "+f"(d[0]), "+f"(d[1]), "+f"(d[2]), "+f"(d[3])
        : "r"(a0), "r"(a1), "r"(a2), "r"(a3), "r"(b0), "r"(b1));
}

// ============================================================================
// prep: capped B matrices + bias + compacted excess lists (deterministic order)
// ============================================================================
__global__ void __launch_bounds__(256)
prep_kernel(const float* __restrict__ centers, const float* __restrict__ stds) {
    const int g = blockIdx.x;
    const int k = threadIdx.x;
    float c = centers[g * IN_DIM + k];
    float s = stds[g * IN_DIM + k];
    float inv  = 1.0f / (s * s);
    float invc = fminf(inv, CAP);
    g_B1[g * IN_DIM + k] = c * invc;
    g_B2[g * IN_DIM + k] = -0.5f * invc;

    __shared__ float red[256];
    red[k] = c * c * invc;
    __syncthreads();
    #pragma unroll
    for (int off = 128; off > 0; off >>= 1) {
        if (k < off) red[k] += red[k + off];
        __syncthreads();
    }
    if (k == 0) g_cst[g] = -0.5f * red[0];

    // ballot-compacted excess list (order = thread order -> deterministic)
    bool pred = inv > CAP;
    const int w = k >> 5, lane = k & 31;
    unsigned mask = __ballot_sync(0xffffffffu, pred);
    __shared__ int wbase[8];
    __shared__ int wcnt[8];
    if (lane == 0) wcnt[w] = __popc(mask);
    __syncthreads();
    if (k == 0) {
        int t = 0;
        #pragma unroll
        for (int i = 0; i < 8; i++) { wbase[i] = t; t += wcnt[i]; }
        g_cnt[g] = t < SLOTS ? t : SLOTS;
    }
    __syncthreads();
    if (pred) {
        int slot = wbase[w] + __popc(mask & ((1u << lane) - 1u));
        if (slot < SLOTS) {
            g_le[g * SLOTS + slot] = -0.5f * (inv - CAP);
            g_lc[g * SLOTS + slot] = c;
            g_lk[g * SLOTS + slot] = k;
        }
    }
}

// ============================================================================
// GEMM1: gauss[b][g] = exp( x.B1 + x^2.B2 + bias + sum_excess e*(x-c)^2 )
// CTA 64(b) x 64(g), persistent swizzled X tile, double-buffered B tiles.
// 256 threads = 8 warps (2m x 4n), warp tile 32x16, dual tf32 mma chains.
// ============================================================================
#define B_ST 20
#define XS_OFF 0                          // 64*256 floats
#define B1_OFF (64 * 256)                 // 2*64*B_ST
#define B2_OFF (B1_OFF + 2 * 64 * B_ST)
#define BS_OFF (B2_OFF + 2 * 64 * B_ST)   // bias 64
#define CN_OFF (BS_OFF + 64)              // cnt 64 (int)
#define LE_OFF (CN_OFF + 64)
#define LC_OFF (LE_OFF + 64 * SLOTS)
#define LK_OFF (LC_OFF + 64 * SLOTS)
#define SMEM_FLOATS (LK_OFF + 64 * SLOTS)
#define SMEM_BYTES (SMEM_FLOATS * 4)

__global__ void __launch_bounds__(256, 1)
gemm1_kernel(const float* __restrict__ x) {
    extern __shared__ float sm[];
    float* Xs    = sm + XS_OFF;
    float* B1s   = sm + B1_OFF;
    float* B2s   = sm + B2_OFF;
    float* biasS = sm + BS_OFF;
    int*   cntS  = (int*)(sm + CN_OFF);
    float* leS   = sm + LE_OFF;
    float* lcS   = sm + LC_OFF;
    int*   lkS   = (int*)(sm + LK_OFF);

    const int tid  = threadIdx.x;
    const int lane = tid & 31;
    const int qr   = lane >> 2;   // 0..7
    const int ql   = lane & 3;    // 0..3
    const int w    = tid >> 5;
    const int wm   = (w >> 2) * 32;
    const int wn   = (w & 3) * 16;
    const int m0   = blockIdx.y * 64;
    const int n0   = blockIdx.x * 64;
    const int lr   = tid >> 2;          // 0..63
    const int lk4  = (tid & 3) * 4;     // 0,4,8,12
    const int swzl = (lr & 7) << 2;
    const int swzf = qr << 2;           // fragment-row swizzle (row&7 == qr)

    // stage X tile (swizzled: col' = col ^ ((row&7)<<2))
    #pragma unroll 4
    for (int it = 0; it < 16; ++it) {
        float4 v = *(const float4*)&x[(m0 + lr) * IN_DIM + it * 16 + lk4];
        *(float4*)&Xs[lr * 256 + ((it * 16 + lk4) ^ swzl)] = v;
    }
    // stage bias/cnt/lists
    if (tid < 64) { biasS[tid] = g_cst[n0 + tid]; cntS[tid] = g_cnt[n0 + tid]; }
    #pragma unroll
    for (int j = 0; j < 4; ++j) {
        int idx = tid + j * 256;            // 0..1023 = 64 gaussians * 16 slots
        leS[idx] = g_le[n0 * SLOTS + idx];
        lcS[idx] = g_lc[n0 * SLOTS + idx];
        lkS[idx] = g_lk[n0 * SLOTS + idx];
    }
    // first B tile
    float4 b1v = *(const float4*)&g_B1[(n0 + lr) * IN_DIM + lk4];
    float4 b2v = *(const float4*)&g_B2[(n0 + lr) * IN_DIM + lk4];
    *(float4*)&B1s[lr * B_ST + lk4] = b1v;
    *(float4*)&B2s[lr * B_ST + lk4] = b2v;
    __syncthreads();

    float acc[2][2][4];
    #pragma unroll
    for (int a = 0; a < 2; a++)
        #pragma unroll
        for (int b = 0; b < 2; b++)
            #pragma unroll
            for (int c = 0; c < 4; c++) acc[a][b][c] = 0.f;

    for (int it = 0; it < 16; ++it) {
        const int buf = it & 1;
        if (it < 15) {
            b1v = *(const float4*)&g_B1[(n0 + lr) * IN_DIM + (it + 1) * 16 + lk4];
            b2v = *(const float4*)&g_B2[(n0 + lr) * IN_DIM + (it + 1) * 16 + lk4];
        }
        #pragma unroll
        for (int ks = 0; ks < 16; ks += 8) {
            const int kc0 = (it * 16 + ks + ql)     ^ swzf;
            const int kc1 = (it * 16 + ks + ql + 4) ^ swzf;
            uint32_t ax[2][4], aq[2][4];
            #pragma unroll
            for (int mt = 0; mt < 2; ++mt) {
                const int r0 = (wm + mt * 16 + qr) * 256;
                float f0 = Xs[r0 + kc0];
                float f1 = Xs[r0 + 2048 + kc0];
                float f2 = Xs[r0 + kc1];
                float f3 = Xs[r0 + 2048 + kc1];
                ax[mt][0] = fbits(f0);      ax[mt][1] = fbits(f1);
                ax[mt][2] = fbits(f2);      ax[mt][3] = fbits(f3);
                aq[mt][0] = fbits(f0 * f0); aq[mt][1] = fbits(f1 * f1);
                aq[mt][2] = fbits(f2 * f2); aq[mt][3] = fbits(f3 * f3);
            }
            #pragma unroll
            for (int nt = 0; nt < 2; ++nt) {
                const int nb = buf * (64 * B_ST) + (wn + nt * 8 + qr) * B_ST;
                uint32_t b10 = fbits(B1s[nb + ks + ql]);
                uint32_t b11 = fbits(B1s[nb + ks + ql + 4]);
                uint32_t b20 = fbits(B2s[nb + ks + ql]);
                uint32_t b21 = fbits(B2s[nb + ks + ql + 4]);
                #pragma unroll
                for (int mt = 0; mt < 2; ++mt) {
                    mma_tf32(acc[mt][nt], ax[mt][0], ax[mt][1], ax[mt][2], ax[mt][3], b10, b11);
                    mma_tf32(acc[mt][nt], aq[mt][0], aq[mt][1], aq[mt][2], aq[mt][3], b20, b21);
                }
            }
        }
        if (it < 15) {
            const int ob = (buf ^ 1) * (64 * B_ST);
            *(float4*)&B1s[ob + lr * B_ST + lk4] = b1v;
            *(float4*)&B2s[ob + lr * B_ST + lk4] = b2v;
        }
        __syncthreads();
    }

    // sparse excess correction: corr[gi][ri] = sum_j e*(x[b_ri,k_j]-c_j)^2
    // gi: g = wn + (gi>>1)*8 + 2*ql + (gi&1);  ri: b-row = wm + (ri>>1)*16 + qr + (ri&1)*8
    float corr[4][4];
    #pragma unroll
    for (int gi = 0; gi < 4; ++gi) {
        const int g   = wn + (gi >> 1) * 8 + 2 * ql + (gi & 1);
        const int cnt = cntS[g];
        float c0 = 0.f, c1 = 0.f, c2 = 0.f, c3 = 0.f;
        for (int j = 0; j < cnt; ++j) {
            float e  = leS[g * SLOTS + j];
            float cc = lcS[g * SLOTS + j];
            int   kx = lkS[g * SLOTS + j] ^ swzf;
            float d0 = Xs[(wm      + qr) * 256 + kx] - cc;
            float d1 = Xs[(wm +  8 + qr) * 256 + kx] - cc;
            float d2 = Xs[(wm + 16 + qr) * 256 + kx] - cc;
            float d3 = Xs[(wm + 24 + qr) * 256 + kx] - cc;
            c0 += e * d0 * d0; c1 += e * d1 * d1;
            c2 += e * d2 * d2; c3 += e * d3 * d3;
        }
        corr[gi][0] = c0; corr[gi][1] = c1; corr[gi][2] = c2; corr[gi][3] = c3;
    }

    // epilogue: exponent = acc + bias + corr; gauss = exp(...)
    #pragma unroll
    for (int mt = 0; mt < 2; ++mt) {
        const int mrow = m0 + wm + mt * 16 + qr;
        #pragma unroll
        for (int nt = 0; nt < 2; ++nt) {
            const int ncol = wn + nt * 8 + 2 * ql;
            const float b0 = biasS[ncol], b1 = biasS[ncol + 1];
            const int g0 = nt * 2, g1 = nt * 2 + 1;
            float2 e0, e1;
            e0.x = expf(acc[mt][nt][0] + b0 + corr[g0][mt * 2]);
            e0.y = expf(acc[mt][nt][1] + b1 + corr[g1][mt * 2]);
            e1.x = expf(acc[mt][nt][2] + b0 + corr[g0][mt * 2 + 1]);
            e1.y = expf(acc[mt][nt][3] + b1 + corr[g1][mt * 2 + 1]);
            *(float2*)&g_gauss[ mrow      * NG + n0 + ncol] = e0;
            *(float2*)&g_gauss[(mrow + 8) * NG + n0 + ncol] = e1;
        }
    }
}

// ============================================================================
// GEMM2: out[b][o] = gauss[b,:] . W[:,o]   (K = 512), tf32 mma
// CTA 64(b) x 32(o), BK=32, 128 threads = 4 warps (2x2), warp tile 32x16.
// ============================================================================
#define G2_SA 36
#define G2_SB 40

__global__ void __launch_bounds__(128, 1)
gemm2_kernel(const float* __restrict__ W, float* __restrict__ out) {
    __shared__ float As[2][64][G2_SA];
    __shared__ float Bs[2][32][G2_SB];

    const int tid  = threadIdx.x;
    const int lane = tid & 31;
    const int qr   = lane >> 2;
    const int ql   = lane & 3;
    const int w    = tid >> 5;
    const int wm   = (w >> 1) * 32;
    const int wn   = (w & 1) * 16;
    const int m0   = blockIdx.y * 64;
    const int n0   = blockIdx.x * 32;
    const int ar   = tid >> 3;        // 0..15
    const int ak   = (tid & 7) * 4;   // 0..28

    float acc[2][2][4];
    #pragma unroll
    for (int a = 0; a < 2; a++)
        #pragma unroll
        for (int b = 0; b < 2; b++)
            #pragma unroll
            for (int c = 0; c < 4; c++) acc[a][b][c] = 0.f;

    float4 av[4], bv[2];
    #pragma unroll
    for (int j = 0; j < 4; ++j)
        av[j] = *(const float4*)&g_gauss[(m0 + ar + 16 * j) * NG + ak];
    #pragma unroll
    for (int j = 0; j < 2; ++j)
        bv[j] = *(const float4*)&W[(ar + 16 * j) * OUT_DIM + n0 + ak];
    #pragma unroll
    for (int j = 0; j < 4; ++j) *(float4*)&As[0][ar + 16 * j][ak] = av[j];
    #pragma unroll
    for (int j = 0; j < 2; ++j) *(float4*)&Bs[0][ar + 16 * j][ak] = bv[j];
    __syncthreads();

    for (int it = 0; it < 16; ++it) {
        const int buf = it & 1;
        if (it < 15) {
            #pragma unroll
            for (int j = 0; j < 4; ++j)
                av[j] = *(const float4*)&g_gauss[(m0 + ar + 16 * j) * NG + (it + 1) * 32 + ak];
            #pragma unroll
            for (int j = 0; j < 2; ++j)
                bv[j] = *(const float4*)&W[((it + 1) * 32 + ar + 16 * j) * OUT_DIM + n0 + ak];
        }
        #pragma unroll
        for (int ks = 0; ks < 32; ks += 8) {
            uint32_t af[2][4];
            #pragma unroll
            for (int mt = 0; mt < 2; ++mt) {
                const int mb = wm + mt * 16;
                af[mt][0] = fbits(As[buf][mb + qr    ][ks + ql    ]);
                af[mt][1] = fbits(As[buf][mb + qr + 8][ks + ql    ]);
                af[mt][2] = fbits(As[buf][mb + qr    ][ks + ql + 4]);
                af[mt][3] = fbits(As[buf][mb + qr + 8][ks + ql + 4]);
            }
            #pragma unroll
            for (int nt = 0; nt < 2; ++nt) {
                const int nb = wn + nt * 8;
                uint32_t b0 = fbits(Bs[buf][ks + ql    ][nb + qr]);
                uint32_t b1 = fbits(Bs[buf][ks + ql + 4][nb + qr]);
                #pragma unroll
                for (int mt = 0; mt < 2; ++mt)
                    mma_tf32(acc[mt][nt], af[mt][0], af[mt][1], af[mt][2], af[mt][3], b0, b1);
            }
        }
        if (it < 15) {
            #pragma unroll
            for (int j = 0; j < 4; ++j) *(float4*)&As[buf ^ 1][ar + 16 * j][ak] = av[j];
            #pragma unroll
            for (int j = 0; j < 2; ++j) *(float4*)&Bs[buf ^ 1][ar + 16 * j][ak] = bv[j];
        }
        __syncthreads();
    }

    #pragma unroll
    for (int mt = 0; mt < 2; ++mt) {
        const int mrow = m0 + wm + mt * 16 + qr;
        #pragma unroll
        for (int nt = 0; nt < 2; ++nt) {
            const int ncol = n0 + wn + nt * 8 + 2 * ql;
            float2 v0 = make_float2(acc[mt][nt][0], acc[mt][nt][1]);
            float2 v1 = make_float2(acc[mt][nt][2], acc[mt][nt][3]);
            *(float2*)&out[ mrow      * OUT_DIM + ncol] = v0;
            *(float2*)&out[(mrow + 8) * OUT_DIM + ncol] = v1;
        }
    }
}

extern "C" void kernel_launch(void* const* d_in, const int* in_sizes, int n_in,
                              void* d_out, int out_size) {
    const float* x       = (const float*)d_in[0];
    const float* centers = (const float*)d_in[1];
    const float* stds    = (const float*)d_in[2];
    const float* weights = (const float*)d_in[3];
    float* out = (float*)d_out;

    cudaFuncSetAttribute(gemm1_kernel,
                         cudaFuncAttributeMaxDynamicSharedMemorySize, SMEM_BYTES);

    prep_kernel<<<NG, 256>>>(centers, stds);
    gemm1_kernel<<<dim3(NG / 64, BATCH / 64), 256, SMEM_BYTES>>>(x);
    gemm2_kernel<<<dim3(OUT_DIM / 32, BATCH / 64), 128>>>(weights, out);
}

// round 6
// speedup vs baseline: 4.2720x; 1.7522x over previous
#include <cuda_runtime.h>
#include <math.h>
#include <stdint.h>

#define BATCH   1024
#define IN_DIM  256
#define NG      512
#define OUT_DIM 256
#define CAP     2048.0f
#define SLOTS   16

__device__ __align__(16) float g_gauss[BATCH * NG];

__device__ __forceinline__ uint32_t fbits(float f) { return __float_as_uint(f); }

__device__ __forceinline__ void mma_tf32(float d[4],
    uint32_t a0, uint32_t a1, uint32_t a2, uint32_t a3,
    uint32_t b0, uint32_t b1) {
    asm volatile(
        "mma.sync.aligned.m16n8k8.row.col.f32.tf32.tf32.f32 "
        "{%0,%1,%2,%3}, {%4,%5,%6,%7}, {%8,%9}, {%0,%1,%2,%3};\n"
        : "+f"(d[0]), "+f"(d[1]), "+f"(d[2]), "+f"(d[3])
        : "r"(a0), "r"(a1), "r"(a2), "r"(a3), "r"(b0), "r"(b1));
}

// ============================================================================
// GEMM1 (prep fully fused): gauss[b][g] =
//   exp( x.(c*invc) + x^2.(-0.5*invc) - 0.5*sum c^2*invc + sum_excess e*(x-c)^2 )
// with invc = min(1/s^2, CAP); excess coords (1/s^2 > CAP) handled exactly in
// fp32 via per-gaussian compacted lists (deterministic quad-ballot order).
// CTA 64(b) x 64(g). All tiles smem-resident; mainloop has NO syncs, NO gmem.
// 256 threads = 8 warps (2m x 4n), warp tile 32x16, dual tf32 mma chains.
// ============================================================================
#define B_ST 260   // 260 mod 32 = 4 -> fragment banks 4*qr+ql, conflict-free
#define XS_OFF 0                          // 64*256
#define B1_OFF (64 * 256)                 // 64*B_ST
#define B2_OFF (B1_OFF + 64 * B_ST)
#define BS_OFF (B2_OFF + 64 * B_ST)       // bias 64
#define CN_OFF (BS_OFF + 64)              // cnt 64 (int)
#define LE_OFF (CN_OFF + 64)
#define LC_OFF (LE_OFF + 64 * SLOTS)
#define LK_OFF (LC_OFF + 64 * SLOTS)
#define SMEM_FLOATS (LK_OFF + 64 * SLOTS)
#define SMEM_BYTES (SMEM_FLOATS * 4)

__global__ void __launch_bounds__(256, 1)
gemm1_kernel(const float* __restrict__ x,
             const float* __restrict__ centers,
             const float* __restrict__ stds) {
    extern __shared__ float sm[];
    float* Xs    = sm + XS_OFF;
    float* B1s   = sm + B1_OFF;
    float* B2s   = sm + B2_OFF;
    float* biasS = sm + BS_OFF;
    int*   cntS  = (int*)(sm + CN_OFF);
    float* leS   = sm + LE_OFF;
    float* lcS   = sm + LC_OFF;
    int*   lkS   = (int*)(sm + LK_OFF);

    const int tid  = threadIdx.x;
    const int lane = tid & 31;
    const int qr   = lane >> 2;   // 0..7
    const int ql   = lane & 3;    // 0..3
    const int w    = tid >> 5;
    const int wm   = (w >> 2) * 32;
    const int wn   = (w & 3) * 16;
    const int m0   = blockIdx.y * 64;
    const int n0   = blockIdx.x * 64;
    const int lr   = tid >> 2;          // row/gaussian 0..63 (4 threads each)
    const int q    = tid & 3;           // thread-in-quad
    const int lk4  = q * 4;             // k sub-offset 0,4,8,12
    const int swzl = (lr & 7) << 2;
    const int swzf = qr << 2;

    // ---- fused staging: X tile + B tiles (computed from c,s) + bias + lists ----
    float bias_part = 0.f;
    int   base      = 0;     // slots used so far for gaussian lr (quad-uniform)
    #pragma unroll 4
    for (int it = 0; it < 16; ++it) {
        const int k0 = it * 16 + lk4;
        float4 xv = *(const float4*)&x[(m0 + lr) * IN_DIM + k0];
        *(float4*)&Xs[lr * 256 + (k0 ^ swzl)] = xv;

        float4 cv = *(const float4*)&centers[(n0 + lr) * IN_DIM + k0];
        float4 sv = *(const float4*)&stds   [(n0 + lr) * IN_DIM + k0];
        float cc[4] = {cv.x, cv.y, cv.z, cv.w};
        float inv[4];
        inv[0] = 1.f / (sv.x * sv.x); inv[1] = 1.f / (sv.y * sv.y);
        inv[2] = 1.f / (sv.z * sv.z); inv[3] = 1.f / (sv.w * sv.w);
        float ic[4];
        float4 b1v, b2v;
        ic[0] = fminf(inv[0], CAP); ic[1] = fminf(inv[1], CAP);
        ic[2] = fminf(inv[2], CAP); ic[3] = fminf(inv[3], CAP);
        b1v = make_float4(cc[0]*ic[0], cc[1]*ic[1], cc[2]*ic[2], cc[3]*ic[3]);
        b2v = make_float4(-0.5f*ic[0], -0.5f*ic[1], -0.5f*ic[2], -0.5f*ic[3]);
        *(float4*)&B1s[lr * B_ST + k0] = b1v;
        *(float4*)&B2s[lr * B_ST + k0] = b2v;
        bias_part -= 0.5f * (cc[0]*cc[0]*ic[0] + cc[1]*cc[1]*ic[1] +
                             cc[2]*cc[2]*ic[2] + cc[3]*cc[3]*ic[3]);

        // deterministic compaction of excess coords (inv > CAP)
        unsigned m = (inv[0] > CAP ? 1u : 0u) | (inv[1] > CAP ? 2u : 0u) |
                     (inv[2] > CAP ? 4u : 0u) | (inv[3] > CAP ? 8u : 0u);
        int cnt = __popc(m);
        const int qb = lane & ~3;
        int c0 = __shfl_sync(0xffffffffu, cnt, qb + 0);
        int c1 = __shfl_sync(0xffffffffu, cnt, qb + 1);
        int c2 = __shfl_sync(0xffffffffu, cnt, qb + 2);
        int c3 = __shfl_sync(0xffffffffu, cnt, qb + 3);
        int prefix = (q > 0 ? c0 : 0) + (q > 1 ? c1 : 0) + (q > 2 ? c2 : 0);
        int slot = base + prefix;
        #pragma unroll
        for (int b = 0; b < 4; ++b) {
            if ((m >> b) & 1u) {
                if (slot < SLOTS) {
                    leS[lr * SLOTS + slot] = -0.5f * (inv[b] - CAP);
                    lcS[lr * SLOTS + slot] = cc[b];
                    lkS[lr * SLOTS + slot] = k0 + b;
                }
                slot++;
            }
        }
        base += c0 + c1 + c2 + c3;
    }
    bias_part += __shfl_xor_sync(0xffffffffu, bias_part, 1);
    bias_part += __shfl_xor_sync(0xffffffffu, bias_part, 2);
    if (q == 0) {
        biasS[lr] = bias_part;
        cntS[lr]  = base < SLOTS ? base : SLOTS;
    }
    __syncthreads();   // the ONLY barrier

    // ---- mainloop: pure LDS + HMMA, no syncs, no gmem ----
    float acc[2][2][4];
    #pragma unroll
    for (int a = 0; a < 2; a++)
        #pragma unroll
        for (int b = 0; b < 2; b++)
            #pragma unroll
            for (int c = 0; c < 4; c++) acc[a][b][c] = 0.f;

    #pragma unroll 2
    for (int it = 0; it < 16; ++it) {
        #pragma unroll
        for (int ks = 0; ks < 16; ks += 8) {
            const int kb  = it * 16 + ks;
            const int kc0 = (kb + ql)     ^ swzf;
            const int kc1 = (kb + ql + 4) ^ swzf;
            uint32_t ax[2][4], aq[2][4];
            #pragma unroll
            for (int mt = 0; mt < 2; ++mt) {
                const int r0 = (wm + mt * 16 + qr) * 256;
                float f0 = Xs[r0 + kc0];
                float f1 = Xs[r0 + 2048 + kc0];
                float f2 = Xs[r0 + kc1];
                float f3 = Xs[r0 + 2048 + kc1];
                ax[mt][0] = fbits(f0);      ax[mt][1] = fbits(f1);
                ax[mt][2] = fbits(f2);      ax[mt][3] = fbits(f3);
                aq[mt][0] = fbits(f0 * f0); aq[mt][1] = fbits(f1 * f1);
                aq[mt][2] = fbits(f2 * f2); aq[mt][3] = fbits(f3 * f3);
            }
            #pragma unroll
            for (int nt = 0; nt < 2; ++nt) {
                const int nb = (wn + nt * 8 + qr) * B_ST + kb;
                uint32_t b10 = fbits(B1s[nb + ql]);
                uint32_t b11 = fbits(B1s[nb + ql + 4]);
                uint32_t b20 = fbits(B2s[nb + ql]);
                uint32_t b21 = fbits(B2s[nb + ql + 4]);
                #pragma unroll
                for (int mt = 0; mt < 2; ++mt) {
                    mma_tf32(acc[mt][nt], ax[mt][0], ax[mt][1], ax[mt][2], ax[mt][3], b10, b11);
                    mma_tf32(acc[mt][nt], aq[mt][0], aq[mt][1], aq[mt][2], aq[mt][3], b20, b21);
                }
            }
        }
    }

    // ---- sparse excess correction (exact fp32, direct form) ----
    float corr[4][4];
    #pragma unroll
    for (int gi = 0; gi < 4; ++gi) {
        const int g   = wn + (gi >> 1) * 8 + 2 * ql + (gi & 1);
        const int cnt = cntS[g];
        float c0 = 0.f, c1 = 0.f, c2 = 0.f, c3 = 0.f;
        for (int j = 0; j < cnt; ++j) {
            float e  = leS[g * SLOTS + j];
            float cc = lcS[g * SLOTS + j];
            int   kx = lkS[g * SLOTS + j] ^ swzf;
            float d0 = Xs[(wm      + qr) * 256 + kx] - cc;
            float d1 = Xs[(wm +  8 + qr) * 256 + kx] - cc;
            float d2 = Xs[(wm + 16 + qr) * 256 + kx] - cc;
            float d3 = Xs[(wm + 24 + qr) * 256 + kx] - cc;
            c0 += e * d0 * d0; c1 += e * d1 * d1;
            c2 += e * d2 * d2; c3 += e * d3 * d3;
        }
        corr[gi][0] = c0; corr[gi][1] = c1; corr[gi][2] = c2; corr[gi][3] = c3;
    }

    // ---- epilogue: bias + corr, exp, store ----
    #pragma unroll
    for (int mt = 0; mt < 2; ++mt) {
        const int mrow = m0 + wm + mt * 16 + qr;
        #pragma unroll
        for (int nt = 0; nt < 2; ++nt) {
            const int ncol = wn + nt * 8 + 2 * ql;
            const float b0 = biasS[ncol], b1 = biasS[ncol + 1];
            const int g0 = nt * 2, g1 = nt * 2 + 1;
            float2 e0, e1;
            e0.x = __expf(acc[mt][nt][0] + b0 + corr[g0][mt * 2]);
            e0.y = __expf(acc[mt][nt][1] + b1 + corr[g1][mt * 2]);
            e1.x = __expf(acc[mt][nt][2] + b0 + corr[g0][mt * 2 + 1]);
            e1.y = __expf(acc[mt][nt][3] + b1 + corr[g1][mt * 2 + 1]);
            *(float2*)&g_gauss[ mrow      * NG + n0 + ncol] = e0;
            *(float2*)&g_gauss[(mrow + 8) * NG + n0 + ncol] = e1;
        }
    }
}

// ============================================================================
// GEMM2: out[b][o] = gauss[b,:] . W[:,o]   (K = 512), tf32 mma
// CTA 64(b) x 32(o), BK=32, 128 threads = 4 warps (2x2), warp tile 32x16.
// ============================================================================
#define G2_SA 36
#define G2_SB 40

__global__ void __launch_bounds__(128, 1)
gemm2_kernel(const float* __restrict__ W, float* __restrict__ out) {
    __shared__ float As[2][64][G2_SA];
    __shared__ float Bs[2][32][G2_SB];

    const int tid  = threadIdx.x;
    const int lane = tid & 31;
    const int qr   = lane >> 2;
    const int ql   = lane & 3;
    const int w    = tid >> 5;
    const int wm   = (w >> 1) * 32;
    const int wn   = (w & 1) * 16;
    const int m0   = blockIdx.y * 64;
    const int n0   = blockIdx.x * 32;
    const int ar   = tid >> 3;        // 0..15
    const int ak   = (tid & 7) * 4;   // 0..28

    float acc[2][2][4];
    #pragma unroll
    for (int a = 0; a < 2; a++)
        #pragma unroll
        for (int b = 0; b < 2; b++)
            #pragma unroll
            for (int c = 0; c < 4; c++) acc[a][b][c] = 0.f;

    float4 av[4], bv[2];
    #pragma unroll
    for (int j = 0; j < 4; ++j)
        av[j] = *(const float4*)&g_gauss[(m0 + ar + 16 * j) * NG + ak];
    #pragma unroll
    for (int j = 0; j < 2; ++j)
        bv[j] = *(const float4*)&W[(ar + 16 * j) * OUT_DIM + n0 + ak];
    #pragma unroll
    for (int j = 0; j < 4; ++j) *(float4*)&As[0][ar + 16 * j][ak] = av[j];
    #pragma unroll
    for (int j = 0; j < 2; ++j) *(float4*)&Bs[0][ar + 16 * j][ak] = bv[j];
    __syncthreads();

    for (int it = 0; it < 16; ++it) {
        const int buf = it & 1;
        if (it < 15) {
            #pragma unroll
            for (int j = 0; j < 4; ++j)
                av[j] = *(const float4*)&g_gauss[(m0 + ar + 16 * j) * NG + (it + 1) * 32 + ak];
            #pragma unroll
            for (int j = 0; j < 2; ++j)
                bv[j] = *(const float4*)&W[((it + 1) * 32 + ar + 16 * j) * OUT_DIM + n0 + ak];
        }
        #pragma unroll
        for (int ks = 0; ks < 32; ks += 8) {
            uint32_t af[2][4];
            #pragma unroll
            for (int mt = 0; mt < 2; ++mt) {
                const int mb = wm + mt * 16;
                af[mt][0] = fbits(As[buf][mb + qr    ][ks + ql    ]);
                af[mt][1] = fbits(As[buf][mb + qr + 8][ks + ql    ]);
                af[mt][2] = fbits(As[buf][mb + qr    ][ks + ql + 4]);
                af[mt][3] = fbits(As[buf][mb + qr + 8][ks + ql + 4]);
            }
            #pragma unroll
            for (int nt = 0; nt < 2; ++nt) {
                const int nb = wn + nt * 8;
                uint32_t b0 = fbits(Bs[buf][ks + ql    ][nb + qr]);
                uint32_t b1 = fbits(Bs[buf][ks + ql + 4][nb + qr]);
                #pragma unroll
                for (int mt = 0; mt < 2; ++mt)
                    mma_tf32(acc[mt][nt], af[mt][0], af[mt][1], af[mt][2], af[mt][3], b0, b1);
            }
        }
        if (it < 15) {
            #pragma unroll
            for (int j = 0; j < 4; ++j) *(float4*)&As[buf ^ 1][ar + 16 * j][ak] = av[j];
            #pragma unroll
            for (int j = 0; j < 2; ++j) *(float4*)&Bs[buf ^ 1][ar + 16 * j][ak] = bv[j];
        }
        __syncthreads();
    }

    #pragma unroll
    for (int mt = 0; mt < 2; ++mt) {
        const int mrow = m0 + wm + mt * 16 + qr;
        #pragma unroll
        for (int nt = 0; nt < 2; ++nt) {
            const int ncol = n0 + wn + nt * 8 + 2 * ql;
            float2 v0 = make_float2(acc[mt][nt][0], acc[mt][nt][1]);
            float2 v1 = make_float2(acc[mt][nt][2], acc[mt][nt][3]);
            *(float2*)&out[ mrow      * OUT_DIM + ncol] = v0;
            *(float2*)&out[(mrow + 8) * OUT_DIM + ncol] = v1;
        }
    }
}

extern "C" void kernel_launch(void* const* d_in, const int* in_sizes, int n_in,
                              void* d_out, int out_size) {
    const float* x       = (const float*)d_in[0];
    const float* centers = (const float*)d_in[1];
    const float* stds    = (const float*)d_in[2];
    const float* weights = (const float*)d_in[3];
    float* out = (float*)d_out;

    static int configured = 0;
    if (!configured) {
        cudaFuncSetAttribute(gemm1_kernel,
                             cudaFuncAttributeMaxDynamicSharedMemorySize, SMEM_BYTES);
        configured = 1;
    }

    gemm1_kernel<<<dim3(NG / 64, BATCH / 64), 256, SMEM_BYTES>>>(x, centers, stds);
    gemm2_kernel<<<dim3(OUT_DIM / 32, BATCH / 64), 128>>>(weights, out);
}

// round 8
// speedup vs baseline: 4.3668x; 1.0222x over previous
#include <cuda_runtime.h>
#include <math.h>
#include <stdint.h>

#define BATCH   1024
#define IN_DIM  256
#define NG      512
#define OUT_DIM 256
#define CAP     2048.0f
#define SLOTS   16

__device__ __align__(16) float g_gauss[BATCH * NG];

__device__ __forceinline__ uint32_t fbits(float f) { return __float_as_uint(f); }

__device__ __forceinline__ void mma_tf32(float d[4],
    uint32_t a0, uint32_t a1, uint32_t a2, uint32_t a3,
    uint32_t b0, uint32_t b1) {
    asm volatile(
        "mma.sync.aligned.m16n8k8.row.col.f32.tf32.tf32.f32 "
        "{%0,%1,%2,%3}, {%4,%5,%6,%7}, {%8,%9}, {%0,%1,%2,%3};\n"
        : "+f"(d[0]), "+f"(d[1]), "+f"(d[2]), "+f"(d[3])
        : "r"(a0), "r"(a1), "r"(a2), "r"(a3), "r"(b0), "r"(b1));
}

__device__ __forceinline__ void cp16(void* smem_dst, const void* gsrc) {
    uint32_t s = (uint32_t)__cvta_generic_to_shared(smem_dst);
    asm volatile("cp.async.cg.shared.global [%0], [%1], 16;\n" :: "r"(s), "l"(gsrc));
}
__device__ __forceinline__ void cp_commit() {
    asm volatile("cp.async.commit_group;\n");
}
template <int N>
__device__ __forceinline__ void cp_wait() {
    asm volatile("cp.async.wait_group %0;\n" :: "n"(N));
}

// ============================================================================
// GEMM1 (prep fully fused) — unchanged from R5 (25.1us total, gemm1 ~7us).
// ============================================================================
#define B_ST 260
#define XS_OFF 0
#define B1_OFF (64 * 256)
#define B2_OFF (B1_OFF + 64 * B_ST)
#define BS_OFF (B2_OFF + 64 * B_ST)
#define CN_OFF (BS_OFF + 64)
#define LE_OFF (CN_OFF + 64)
#define LC_OFF (LE_OFF + 64 * SLOTS)
#define LK_OFF (LC_OFF + 64 * SLOTS)
#define SMEM_FLOATS (LK_OFF + 64 * SLOTS)
#define SMEM_BYTES (SMEM_FLOATS * 4)

__global__ void __launch_bounds__(256, 1)
gemm1_kernel(const float* __restrict__ x,
             const float* __restrict__ centers,
             const float* __restrict__ stds) {
    extern __shared__ float sm[];
    float* Xs    = sm + XS_OFF;
    float* B1s   = sm + B1_OFF;
    float* B2s   = sm + B2_OFF;
    float* biasS = sm + BS_OFF;
    int*   cntS  = (int*)(sm + CN_OFF);
    float* leS   = sm + LE_OFF;
    float* lcS   = sm + LC_OFF;
    int*   lkS   = (int*)(sm + LK_OFF);

    const int tid  = threadIdx.x;
    const int lane = tid & 31;
    const int qr   = lane >> 2;
    const int ql   = lane & 3;
    const int w    = tid >> 5;
    const int wm   = (w >> 2) * 32;
    const int wn   = (w & 3) * 16;
    const int m0   = blockIdx.y * 64;
    const int n0   = blockIdx.x * 64;
    const int lr   = tid >> 2;
    const int q    = tid & 3;
    const int lk4  = q * 4;
    const int swzl = (lr & 7) << 2;
    const int swzf = qr << 2;

    float bias_part = 0.f;
    int   base      = 0;
    #pragma unroll 4
    for (int it = 0; it < 16; ++it) {
        const int k0 = it * 16 + lk4;
        float4 xv = *(const float4*)&x[(m0 + lr) * IN_DIM + k0];
        *(float4*)&Xs[lr * 256 + (k0 ^ swzl)] = xv;

        float4 cv = *(const float4*)&centers[(n0 + lr) * IN_DIM + k0];
        float4 sv = *(const float4*)&stds   [(n0 + lr) * IN_DIM + k0];
        float cc[4] = {cv.x, cv.y, cv.z, cv.w};
        float inv[4];
        inv[0] = 1.f / (sv.x * sv.x); inv[1] = 1.f / (sv.y * sv.y);
        inv[2] = 1.f / (sv.z * sv.z); inv[3] = 1.f / (sv.w * sv.w);
        float ic[4];
        float4 b1v, b2v;
        ic[0] = fminf(inv[0], CAP); ic[1] = fminf(inv[1], CAP);
        ic[2] = fminf(inv[2], CAP); ic[3] = fminf(inv[3], CAP);
        b1v = make_float4(cc[0]*ic[0], cc[1]*ic[1], cc[2]*ic[2], cc[3]*ic[3]);
        b2v = make_float4(-0.5f*ic[0], -0.5f*ic[1], -0.5f*ic[2], -0.5f*ic[3]);
        *(float4*)&B1s[lr * B_ST + k0] = b1v;
        *(float4*)&B2s[lr * B_ST + k0] = b2v;
        bias_part -= 0.5f * (cc[0]*cc[0]*ic[0] + cc[1]*cc[1]*ic[1] +
                             cc[2]*cc[2]*ic[2] + cc[3]*cc[3]*ic[3]);

        unsigned m = (inv[0] > CAP ? 1u : 0u) | (inv[1] > CAP ? 2u : 0u) |
                     (inv[2] > CAP ? 4u : 0u) | (inv[3] > CAP ? 8u : 0u);
        int cnt = __popc(m);
        const int qb = lane & ~3;
        int c0 = __shfl_sync(0xffffffffu, cnt, qb + 0);
        int c1 = __shfl_sync(0xffffffffu, cnt, qb + 1);
        int c2 = __shfl_sync(0xffffffffu, cnt, qb + 2);
        int c3 = __shfl_sync(0xffffffffu, cnt, qb + 3);
        int prefix = (q > 0 ? c0 : 0) + (q > 1 ? c1 : 0) + (q > 2 ? c2 : 0);
        int slot = base + prefix;
        #pragma unroll
        for (int b = 0; b < 4; ++b) {
            if ((m >> b) & 1u) {
                if (slot < SLOTS) {
                    leS[lr * SLOTS + slot] = -0.5f * (inv[b] - CAP);
                    lcS[lr * SLOTS + slot] = cc[b];
                    lkS[lr * SLOTS + slot] = k0 + b;
                }
                slot++;
            }
        }
        base += c0 + c1 + c2 + c3;
    }
    bias_part += __shfl_xor_sync(0xffffffffu, bias_part, 1);
    bias_part += __shfl_xor_sync(0xffffffffu, bias_part, 2);
    if (q == 0) {
        biasS[lr] = bias_part;
        cntS[lr]  = base < SLOTS ? base : SLOTS;
    }
    __syncthreads();

    float acc[2][2][4];
    #pragma unroll
    for (int a = 0; a < 2; a++)
        #pragma unroll
        for (int b = 0; b < 2; b++)
            #pragma unroll
            for (int c = 0; c < 4; c++) acc[a][b][c] = 0.f;

    #pragma unroll 2
    for (int it = 0; it < 16; ++it) {
        #pragma unroll
        for (int ks = 0; ks < 16; ks += 8) {
            const int kb  = it * 16 + ks;
            const int kc0 = (kb + ql)     ^ swzf;
            const int kc1 = (kb + ql + 4) ^ swzf;
            uint32_t ax[2][4], aq[2][4];
            #pragma unroll
            for (int mt = 0; mt < 2; ++mt) {
                const int r0 = (wm + mt * 16 + qr) * 256;
                float f0 = Xs[r0 + kc0];
                float f1 = Xs[r0 + 2048 + kc0];
                float f2 = Xs[r0 + kc1];
                float f3 = Xs[r0 + 2048 + kc1];
                ax[mt][0] = fbits(f0);      ax[mt][1] = fbits(f1);
                ax[mt][2] = fbits(f2);      ax[mt][3] = fbits(f3);
                aq[mt][0] = fbits(f0 * f0); aq[mt][1] = fbits(f1 * f1);
                aq[mt][2] = fbits(f2 * f2); aq[mt][3] = fbits(f3 * f3);
            }
            #pragma unroll
            for (int nt = 0; nt < 2; ++nt) {
                const int nb = (wn + nt * 8 + qr) * B_ST + kb;
                uint32_t b10 = fbits(B1s[nb + ql]);
                uint32_t b11 = fbits(B1s[nb + ql + 4]);
                uint32_t b20 = fbits(B2s[nb + ql]);
                uint32_t b21 = fbits(B2s[nb + ql + 4]);
                #pragma unroll
                for (int mt = 0; mt < 2; ++mt) {
                    mma_tf32(acc[mt][nt], ax[mt][0], ax[mt][1], ax[mt][2], ax[mt][3], b10, b11);
                    mma_tf32(acc[mt][nt], aq[mt][0], aq[mt][1], aq[mt][2], aq[mt][3], b20, b21);
                }
            }
        }
    }

    float corr[4][4];
    #pragma unroll
    for (int gi = 0; gi < 4; ++gi) {
        const int g   = wn + (gi >> 1) * 8 + 2 * ql + (gi & 1);
        const int cnt = cntS[g];
        float c0 = 0.f, c1 = 0.f, c2 = 0.f, c3 = 0.f;
        for (int j = 0; j < cnt; ++j) {
            float e  = leS[g * SLOTS + j];
            float cc = lcS[g * SLOTS + j];
            int   kx = lkS[g * SLOTS + j] ^ swzf;
            float d0 = Xs[(wm      + qr) * 256 + kx] - cc;
            float d1 = Xs[(wm +  8 + qr) * 256 + kx] - cc;
            float d2 = Xs[(wm + 16 + qr) * 256 + kx] - cc;
            float d3 = Xs[(wm + 24 + qr) * 256 + kx] - cc;
            c0 += e * d0 * d0; c1 += e * d1 * d1;
            c2 += e * d2 * d2; c3 += e * d3 * d3;
        }
        corr[gi][0] = c0; corr[gi][1] = c1; corr[gi][2] = c2; corr[gi][3] = c3;
    }

    #pragma unroll
    for (int mt = 0; mt < 2; ++mt) {
        const int mrow = m0 + wm + mt * 16 + qr;
        #pragma unroll
        for (int nt = 0; nt < 2; ++nt) {
            const int ncol = wn + nt * 8 + 2 * ql;
            const float b0 = biasS[ncol], b1 = biasS[ncol + 1];
            const int g0 = nt * 2, g1 = nt * 2 + 1;
            float2 e0, e1;
            e0.x = __expf(acc[mt][nt][0] + b0 + corr[g0][mt * 2]);
            e0.y = __expf(acc[mt][nt][1] + b1 + corr[g1][mt * 2]);
            e1.x = __expf(acc[mt][nt][2] + b0 + corr[g0][mt * 2 + 1]);
            e1.y = __expf(acc[mt][nt][3] + b1 + corr[g1][mt * 2 + 1]);
            *(float2*)&g_gauss[ mrow      * NG + n0 + ncol] = e0;
            *(float2*)&g_gauss[(mrow + 8) * NG + n0 + ncol] = e1;
        }
    }
}

// ============================================================================
// GEMM2 v2: out[b][o] = gauss[b,:] . W[:,o]   (K = 512), tf32 mma
// CTA 64(m) x 32(n), 256 threads = 8 warps as 4m x 2n (warp tile 16x16).
// 3-stage cp.async pipeline, BK=32, grid 128 CTAs, 8 warps/SM.
// ============================================================================
#define G2_SA 36
#define G2_SB 40
#define G2_STAGES 3
#define G2_ITERS 16   // K=512 / BK=32

__global__ void __launch_bounds__(256, 1)
gemm2_kernel(const float* __restrict__ W, float* __restrict__ out) {
    __shared__ float As[G2_STAGES][64][G2_SA];
    __shared__ float Bs[G2_STAGES][32][G2_SB];

    const int tid  = threadIdx.x;
    const int lane = tid & 31;
    const int qr   = lane >> 2;
    const int ql   = lane & 3;
    const int w    = tid >> 5;
    const int wm   = (w >> 1) * 16;   // 0,16,32,48
    const int wn   = (w & 1) * 16;    // 0,16
    const int m0   = blockIdx.y * 64;
    const int n0   = blockIdx.x * 32;

    // loader mapping
    const int ar = tid >> 2;          // A row 0..63
    const int ak = (tid & 3) * 4;     // A k sub 0,4,8,12 (+16 second half)
    const int br = tid >> 3;          // B k-row 0..31
    const int bn = (tid & 7) * 4;     // B n sub 0..28

    const float* Ag = g_gauss + (m0 + ar) * NG + ak;
    const float* Bg = W + br * OUT_DIM + n0 + bn;

    auto issue_stage = [&](int s, int it) {
        const int k0 = it * 32;
        cp16(&As[s][ar][ak],      Ag + k0);
        cp16(&As[s][ar][ak + 16], Ag + k0 + 16);
        cp16(&Bs[s][br][bn],      Bg + k0 * OUT_DIM);
    };

    issue_stage(0, 0); cp_commit();
    issue_stage(1, 1); cp_commit();

    float acc[2][4] = {};

    for (int it = 0; it < G2_ITERS; ++it) {
        const int buf = it % G2_STAGES;
        cp_wait<1>();
        __syncthreads();

        #pragma unroll
        for (int ks = 0; ks < 32; ks += 8) {
            uint32_t a0 = fbits(As[buf][wm + qr    ][ks + ql    ]);
            uint32_t a1 = fbits(As[buf][wm + qr + 8][ks + ql    ]);
            uint32_t a2 = fbits(As[buf][wm + qr    ][ks + ql + 4]);
            uint32_t a3 = fbits(As[buf][wm + qr + 8][ks + ql + 4]);
            #pragma unroll
            for (int nt = 0; nt < 2; ++nt) {
                const int nb = wn + nt * 8;
                uint32_t b0 = fbits(Bs[buf][ks + ql    ][nb + qr]);
                uint32_t b1 = fbits(Bs[buf][ks + ql + 4][nb + qr]);
                mma_tf32(acc[nt], a0, a1, a2, a3, b0, b1);
            }
        }

        if (it + 2 < G2_ITERS) issue_stage((it + 2) % G2_STAGES, it + 2);
        cp_commit();
    }

    const int mrow = m0 + wm + qr;
    #pragma unroll
    for (int nt = 0; nt < 2; ++nt) {
        const int ncol = n0 + wn + nt * 8 + 2 * ql;
        *(float2*)&out[ mrow      * OUT_DIM + ncol] = make_float2(acc[nt][0], acc[nt][1]);
        *(float2*)&out[(mrow + 8) * OUT_DIM + ncol] = make_float2(acc[nt][2], acc[nt][3]);
    }
}

extern "C" void kernel_launch(void* const* d_in, const int* in_sizes, int n_in,
                              void* d_out, int out_size) {
    const float* x       = (const float*)d_in[0];
    const float* centers = (const float*)d_in[1];
    const float* stds    = (const float*)d_in[2];
    const float* weights = (const float*)d_in[3];
    float* out = (float*)d_out;

    static int configured = 0;
    if (!configured) {
        cudaFuncSetAttribute(gemm1_kernel,
                             cudaFuncAttributeMaxDynamicSharedMemorySize, SMEM_BYTES);
        configured = 1;
    }

    gemm1_kernel<<<dim3(NG / 64, BATCH / 64), 256, SMEM_BYTES>>>(x, centers, stds);
    gemm2_kernel<<<dim3(OUT_DIM / 32, BATCH / 64), 256>>>(weights, out);
}